// round 1
// baseline (speedup 1.0000x reference)
#include <cuda_runtime.h>
#include <cuda_bf16.h>
#include <math_constants.h>

// Problem constants
#define BB   32
#define SS   1024
#define EE   512
#define HH   8
#define DD   64
#define LL   2
#define MM   (BB*SS)            // 32768
#define ELEMS ((size_t)MM*EE)   // 16,777,216

// Scratch (device globals; no allocation allowed)
__device__ float g_X[MM*EE];
__device__ float g_Q[MM*EE];
__device__ float g_K[MM*EE];
__device__ float g_V[MM*EE];
__device__ float g_A[MM*EE];

// ---------------------------------------------------------------------------
// 1) Embedding gather + positional encoding
// ---------------------------------------------------------------------------
__global__ void embed_pe_kernel(const int* __restrict__ inp,
                                const float* __restrict__ table,
                                float* __restrict__ X)
{
    int idx = blockIdx.x * 256 + threadIdx.x;          // over MM*EE
    int c  = idx & (EE - 1);
    int ms = idx >> 9;                                  // row in [0, MM)
    int s  = ms & (SS - 1);
    int tok = inp[ms];
    int i = c >> 1;
    // div_term[i] = exp(2i * (-ln(10000)/E))
    float div = __expf((float)(2 * i) * (-9.210340371976184f / (float)EE));
    float ang = (float)s * div;
    float pe = (c & 1) ? cosf(ang) : sinf(ang);
    X[idx] = table[(size_t)tok * EE + c] + pe;
}

// ---------------------------------------------------------------------------
// 2) SGEMM: C[M,512] = A[M,512] @ W[512,512] (+bias) (+residual/relu epilogue)
//    BM=BN=128, BK=8, 256 threads, 8x8 microtile (split halves).
//    epi==0:  C = acc + bias
//    epi==1:  C = resid + relu(acc + bias)
// ---------------------------------------------------------------------------
__global__ __launch_bounds__(256) void gemm512_kernel(
    const float* __restrict__ A, const float* __restrict__ W,
    const float* __restrict__ bias, const float* __restrict__ resid,
    float* __restrict__ C, int epi)
{
    __shared__ float As[8][128];   // [k][m] (transposed)
    __shared__ float Bs[8][128];   // [k][n]

    const int tid = threadIdx.x;
    const int ty = tid >> 4;         // 0..15
    const int tx = tid & 15;         // 0..15
    const int m0 = blockIdx.y * 128;
    const int n0 = blockIdx.x * 128;

    const int aRow = tid >> 1;           // 0..127
    const int aCol = (tid & 1) * 4;      // 0 or 4
    const int bRow = tid >> 5;           // 0..7
    const int bCol = (tid & 31) * 4;     // 0..124

    float acc[8][8];
    #pragma unroll
    for (int r = 0; r < 8; r++)
        #pragma unroll
        for (int c = 0; c < 8; c++) acc[r][c] = 0.0f;

    const float* Aptr = A + (size_t)(m0 + aRow) * EE + aCol;
    const float* Wptr = W + (size_t)bRow * EE + n0 + bCol;

    for (int kt = 0; kt < EE; kt += 8) {
        float4 av = *(const float4*)(Aptr + kt);
        float4 bv = *(const float4*)(Wptr + (size_t)kt * EE);
        __syncthreads();
        As[aCol + 0][aRow] = av.x;
        As[aCol + 1][aRow] = av.y;
        As[aCol + 2][aRow] = av.z;
        As[aCol + 3][aRow] = av.w;
        *(float4*)&Bs[bRow][bCol] = bv;
        __syncthreads();
        #pragma unroll
        for (int kk = 0; kk < 8; kk++) {
            float4 a0 = *(const float4*)&As[kk][ty * 4];
            float4 a1 = *(const float4*)&As[kk][ty * 4 + 64];
            float4 b0 = *(const float4*)&Bs[kk][tx * 4];
            float4 b1 = *(const float4*)&Bs[kk][tx * 4 + 64];
            float ar[8] = {a0.x, a0.y, a0.z, a0.w, a1.x, a1.y, a1.z, a1.w};
            float br[8] = {b0.x, b0.y, b0.z, b0.w, b1.x, b1.y, b1.z, b1.w};
            #pragma unroll
            for (int r = 0; r < 8; r++)
                #pragma unroll
                for (int c = 0; c < 8; c++)
                    acc[r][c] = fmaf(ar[r], br[c], acc[r][c]);
        }
    }

    float4 bias0 = *(const float4*)&bias[n0 + tx * 4];
    float4 bias1 = *(const float4*)&bias[n0 + tx * 4 + 64];
    float bb[8] = {bias0.x, bias0.y, bias0.z, bias0.w,
                   bias1.x, bias1.y, bias1.z, bias1.w};

    #pragma unroll
    for (int r = 0; r < 8; r++) {
        int row = m0 + ((r < 4) ? (ty * 4 + r) : (64 + ty * 4 + r - 4));
        #pragma unroll
        for (int ch = 0; ch < 2; ch++) {
            int col = n0 + tx * 4 + ch * 64;
            float4 v;
            v.x = acc[r][ch * 4 + 0] + bb[ch * 4 + 0];
            v.y = acc[r][ch * 4 + 1] + bb[ch * 4 + 1];
            v.z = acc[r][ch * 4 + 2] + bb[ch * 4 + 2];
            v.w = acc[r][ch * 4 + 3] + bb[ch * 4 + 3];
            if (epi == 1) {
                float4 rr = *(const float4*)&resid[(size_t)row * EE + col];
                v.x = rr.x + fmaxf(v.x, 0.0f);
                v.y = rr.y + fmaxf(v.y, 0.0f);
                v.z = rr.z + fmaxf(v.z, 0.0f);
                v.w = rr.w + fmaxf(v.w, 0.0f);
            }
            *(float4*)&C[(size_t)row * EE + col] = v;
        }
    }
}

// ---------------------------------------------------------------------------
// 3) Causal flash attention, 64x64 Q tile per CTA, D=64.
//    grid: (S/64, H, B), 256 threads, 16x16 thread grid, 4x4 microtile.
//    Smem: Qs[64][65], Ks[64][65] (reused for P), Vs[64][65] => 49,920 B.
// ---------------------------------------------------------------------------
#define ATT_SMEM (3 * 64 * 65 * 4)

__global__ __launch_bounds__(256) void attn_kernel(
    const float* __restrict__ Q, const float* __restrict__ K,
    const float* __restrict__ V, float* __restrict__ Out)
{
    extern __shared__ float sm[];
    float* Qs = sm;               // stride 65
    float* Ks = sm + 64 * 65;     // stride 65 (also holds P)
    float* Vs = sm + 2 * 64 * 65; // stride 65

    const int qb = blockIdx.x, h = blockIdx.y, b = blockIdx.z;
    const int tid = threadIdx.x;
    const int ty = tid >> 4, tx = tid & 15;
    const int q0 = qb * 64;
    const size_t base = ((size_t)b * SS) * EE + h * DD;

    // Load Q tile
    for (int e = tid; e < 64 * 64; e += 256) {
        int r = e >> 6, c = e & 63;
        Qs[r * 65 + c] = Q[base + (size_t)(q0 + r) * EE + c];
    }

    float mrow[4], lrow[4], o[4][4];
    #pragma unroll
    for (int r = 0; r < 4; r++) {
        mrow[r] = -CUDART_INF_F;
        lrow[r] = 0.0f;
        #pragma unroll
        for (int c = 0; c < 4; c++) o[r][c] = 0.0f;
    }

    for (int t = 0; t <= qb; t++) {
        const int k0 = t * 64;
        __syncthreads();   // prev-iter smem reads done (also guards first-iter Q)
        for (int e = tid; e < 64 * 64; e += 256) {
            int r = e >> 6, c = e & 63;
            size_t g = base + (size_t)(k0 + r) * EE + c;
            Ks[r * 65 + c] = K[g];
            Vs[r * 65 + c] = V[g];
        }
        __syncthreads();

        // S = Q K^T  (4x4 per thread)
        float accS[4][4];
        #pragma unroll
        for (int r = 0; r < 4; r++)
            #pragma unroll
            for (int c = 0; c < 4; c++) accS[r][c] = 0.0f;

        #pragma unroll 8
        for (int d = 0; d < 64; d++) {
            float ar[4], br[4];
            #pragma unroll
            for (int r = 0; r < 4; r++) ar[r] = Qs[(ty * 4 + r) * 65 + d];
            #pragma unroll
            for (int c = 0; c < 4; c++) br[c] = Ks[(tx * 4 + c) * 65 + d];
            #pragma unroll
            for (int r = 0; r < 4; r++)
                #pragma unroll
                for (int c = 0; c < 4; c++)
                    accS[r][c] = fmaf(ar[r], br[c], accS[r][c]);
        }

        // scale + causal mask + online softmax
        float p[4][4];
        const bool diag = (t == qb);
        #pragma unroll
        for (int r = 0; r < 4; r++) {
            float mx = -CUDART_INF_F;
            #pragma unroll
            for (int c = 0; c < 4; c++) {
                float s = accS[r][c] * 0.125f;
                if (diag && (tx * 4 + c) > (ty * 4 + r)) s = -CUDART_INF_F;
                accS[r][c] = s;
                mx = fmaxf(mx, s);
            }
            #pragma unroll
            for (int off = 8; off > 0; off >>= 1)
                mx = fmaxf(mx, __shfl_xor_sync(0xffffffffu, mx, off, 16));
            float mnew = fmaxf(mrow[r], mx);
            float alpha = __expf(mrow[r] - mnew);
            mrow[r] = mnew;
            float ls = 0.0f;
            #pragma unroll
            for (int c = 0; c < 4; c++) {
                float pv = __expf(accS[r][c] - mnew);
                p[r][c] = pv;
                ls += pv;
            }
            #pragma unroll
            for (int off = 8; off > 0; off >>= 1)
                ls += __shfl_xor_sync(0xffffffffu, ls, off, 16);
            lrow[r] = lrow[r] * alpha + ls;
            #pragma unroll
            for (int c = 0; c < 4; c++) o[r][c] *= alpha;
        }

        __syncthreads();   // everyone done reading Ks as K
        #pragma unroll
        for (int r = 0; r < 4; r++)
            #pragma unroll
            for (int c = 0; c < 4; c++)
                Ks[(ty * 4 + r) * 65 + (tx * 4 + c)] = p[r][c];
        __syncthreads();

        // O += P V   (P in Ks, V in Vs)
        #pragma unroll 8
        for (int j = 0; j < 64; j++) {
            float pr[4], vv[4];
            #pragma unroll
            for (int r = 0; r < 4; r++) pr[r] = Ks[(ty * 4 + r) * 65 + j];
            #pragma unroll
            for (int c = 0; c < 4; c++) vv[c] = Vs[j * 65 + tx * 4 + c];
            #pragma unroll
            for (int r = 0; r < 4; r++)
                #pragma unroll
                for (int c = 0; c < 4; c++)
                    o[r][c] = fmaf(pr[r], vv[c], o[r][c]);
        }
    }

    // Write output: Out[b, q, h, :] (row layout [M, E])
    #pragma unroll
    for (int r = 0; r < 4; r++) {
        float inv = 1.0f / lrow[r];
        float4 v;
        v.x = o[r][0] * inv; v.y = o[r][1] * inv;
        v.z = o[r][2] * inv; v.w = o[r][3] * inv;
        *(float4*)&Out[base + (size_t)(q0 + ty * 4 + r) * EE + tx * 4] = v;
    }
}

// ---------------------------------------------------------------------------
// 4) Final projection: out[m] = dot(X[m,:], Wout[:,0]) + b_out[0]
//    one warp per row
// ---------------------------------------------------------------------------
__global__ __launch_bounds__(256) void outproj_kernel(
    const float* __restrict__ X, const float* __restrict__ Wout,
    const float* __restrict__ bout, float* __restrict__ out)
{
    int row  = blockIdx.x * 8 + (threadIdx.x >> 5);
    int lane = threadIdx.x & 31;
    const float* xr = X + (size_t)row * EE;
    float s = 0.0f;
    #pragma unroll
    for (int k = lane; k < EE; k += 32)
        s = fmaf(xr[k], Wout[k], s);
    #pragma unroll
    for (int off = 16; off > 0; off >>= 1)
        s += __shfl_xor_sync(0xffffffffu, s, off);
    if (lane == 0) out[row] = s + bout[0];
}

// ---------------------------------------------------------------------------
// Launcher
// ---------------------------------------------------------------------------
extern "C" void kernel_launch(void* const* d_in, const int* in_sizes, int n_in,
                              void* d_out, int out_size)
{
    const int*   inp   = (const int*)  d_in[0];
    const float* table = (const float*)d_in[1];
    const float* Wq    = (const float*)d_in[2];
    const float* bq    = (const float*)d_in[3];
    const float* Wk    = (const float*)d_in[4];
    const float* bk    = (const float*)d_in[5];
    const float* Wv    = (const float*)d_in[6];
    const float* bv    = (const float*)d_in[7];
    const float* Wo    = (const float*)d_in[8];
    const float* bo    = (const float*)d_in[9];
    const float* Wout  = (const float*)d_in[10];
    const float* bout  = (const float*)d_in[11];
    float* out = (float*)d_out;

    float *pX, *pQ, *pK, *pV, *pA;
    cudaGetSymbolAddress((void**)&pX, g_X);
    cudaGetSymbolAddress((void**)&pQ, g_Q);
    cudaGetSymbolAddress((void**)&pK, g_K);
    cudaGetSymbolAddress((void**)&pV, g_V);
    cudaGetSymbolAddress((void**)&pA, g_A);

    cudaFuncSetAttribute(attn_kernel,
                         cudaFuncAttributeMaxDynamicSharedMemorySize, ATT_SMEM);

    embed_pe_kernel<<<(int)(ELEMS / 256), 256>>>(inp, table, pX);

    dim3 ggrid(EE / 128, MM / 128);      // (4, 256)
    dim3 agrid(SS / 64, HH, BB);         // (16, 8, 32)

    for (int l = 0; l < LL; l++) {
        const float* wq = Wq + (size_t)l * EE * EE;
        const float* wk = Wk + (size_t)l * EE * EE;
        const float* wv = Wv + (size_t)l * EE * EE;
        const float* wo = Wo + (size_t)l * EE * EE;
        gemm512_kernel<<<ggrid, 256>>>(pX, wq, bq + l * EE, pX, pQ, 0);
        gemm512_kernel<<<ggrid, 256>>>(pX, wk, bk + l * EE, pX, pK, 0);
        gemm512_kernel<<<ggrid, 256>>>(pX, wv, bv + l * EE, pX, pV, 0);
        attn_kernel<<<agrid, 256, ATT_SMEM>>>(pQ, pK, pV, pA);
        gemm512_kernel<<<ggrid, 256>>>(pA, wo, bo + l * EE, pX, pX, 1);
    }

    outproj_kernel<<<MM / 8, 256>>>(pX, Wout, bout, out);
}

// round 5
// speedup vs baseline: 1.2157x; 1.2157x over previous
#include <cuda_runtime.h>
#include <cuda_bf16.h>
#include <math_constants.h>
#include <cstdint>

// Problem constants
#define BB   32
#define SS   1024
#define EE   512
#define HH   8
#define DD   64
#define LL   2
#define MM   (BB*SS)            // 32768
#define ELEMS ((size_t)MM*EE)   // 16,777,216

// Scratch (device globals; no allocation allowed)
__device__ float g_X[MM*EE];
__device__ float g_Q[MM*EE];
__device__ float g_K[MM*EE];
__device__ float g_V[MM*EE];
__device__ float g_A[MM*EE];

// ---------------------------------------------------------------------------
// 1) Embedding gather + positional encoding
// ---------------------------------------------------------------------------
__global__ void embed_pe_kernel(const int* __restrict__ inp,
                                const float* __restrict__ table,
                                float* __restrict__ X)
{
    int idx = blockIdx.x * 256 + threadIdx.x;          // over MM*EE
    int c  = idx & (EE - 1);
    int ms = idx >> 9;                                  // row in [0, MM)
    int s  = ms & (SS - 1);
    int tok = inp[ms];
    int i = c >> 1;
    float div = __expf((float)(2 * i) * (-9.210340371976184f / (float)EE));
    float ang = (float)s * div;
    float pe = (c & 1) ? cosf(ang) : sinf(ang);
    X[idx] = table[(size_t)tok * EE + c] + pe;
}

// ---------------------------------------------------------------------------
// 2) Tensor-core SGEMM via tf32x3 (full fp32-equivalent accuracy)
//    C[M,512] = A[M,512] @ W[512,512] (+bias) (+residual/relu epilogue)
//    BM=BN=128, BK=32, 256 threads, warp grid 2(m)x4(n), warp tile 64x32,
//    mma.sync.m16n8k8 tf32, 3-pass split (hi*hi + hi*lo + lo*hi).
//    cp.async double-buffered smem. As layout [m][36], Bs [k][136].
// ---------------------------------------------------------------------------
#define AS_STRIDE 36
#define BS_STRIDE 136
#define AS_BUF (128 * AS_STRIDE)   // floats per buffer
#define BS_BUF (32 * BS_STRIDE)
#define SMEM_GEMM ((2 * AS_BUF + 2 * BS_BUF) * 4)   // 71,680 bytes

__device__ __forceinline__ void split3(float x, uint32_t& hi, uint32_t& lo)
{
    uint32_t xb = __float_as_uint(x);
    hi = xb & 0xFFFFE000u;                 // truncate to tf32
    lo = __float_as_uint(x - __uint_as_float(hi));   // exact residual
}

__device__ __forceinline__ void mma8(float* d, const uint32_t* a,
                                     uint32_t b0, uint32_t b1)
{
    asm volatile(
        "mma.sync.aligned.m16n8k8.row.col.f32.tf32.tf32.f32 "
        "{%0,%1,%2,%3}, {%4,%5,%6,%7}, {%8,%9}, {%0,%1,%2,%3};"
        : "+f"(d[0]), "+f"(d[1]), "+f"(d[2]), "+f"(d[3])
        : "r"(a[0]), "r"(a[1]), "r"(a[2]), "r"(a[3]), "r"(b0), "r"(b1));
}

__global__ __launch_bounds__(256) void gemm512_tc_kernel(
    const float* __restrict__ A, const float* __restrict__ W,
    const float* __restrict__ bias, const float* __restrict__ resid,
    float* __restrict__ C, int epi)
{
    extern __shared__ float sm[];
    float* As = sm;                 // [2][128][AS_STRIDE]
    float* Bs = sm + 2 * AS_BUF;    // [2][32][BS_STRIDE]

    const int tid  = threadIdx.x;
    const int lane = tid & 31;
    const int warp = tid >> 5;
    const int wm = warp & 1;        // 0..1
    const int wn = warp >> 1;       // 0..3
    const int qr = lane >> 2;       // 0..7
    const int qc = lane & 3;        // 0..3
    const int m0 = blockIdx.y * 128;
    const int n0 = blockIdx.x * 128;

    float acc[4][4][4];
    #pragma unroll
    for (int i = 0; i < 4; i++)
        #pragma unroll
        for (int j = 0; j < 4; j++)
            #pragma unroll
            for (int r = 0; r < 4; r++) acc[i][j][r] = 0.0f;

    auto issue = [&](int it) {
        int buf = it & 1;
        int k0 = it * 32;
        float* Asb = As + buf * AS_BUF;
        float* Bsb = Bs + buf * BS_BUF;
        #pragma unroll
        for (int p = 0; p < 4; p++) {
            int id = p * 256 + tid;
            int am = id >> 3, akc = id & 7;
            uint32_t sa = (uint32_t)__cvta_generic_to_shared(Asb + am * AS_STRIDE + akc * 4);
            const float* ga = A + (size_t)(m0 + am) * EE + k0 + akc * 4;
            asm volatile("cp.async.cg.shared.global [%0], [%1], 16;" :: "r"(sa), "l"(ga));
            int bk = id >> 5, bnc = id & 31;
            uint32_t sb = (uint32_t)__cvta_generic_to_shared(Bsb + bk * BS_STRIDE + bnc * 4);
            const float* gb = W + (size_t)(k0 + bk) * EE + n0 + bnc * 4;
            asm volatile("cp.async.cg.shared.global [%0], [%1], 16;" :: "r"(sb), "l"(gb));
        }
        asm volatile("cp.async.commit_group;");
    };

    issue(0);

    for (int it = 0; it < 16; it++) {
        asm volatile("cp.async.wait_group 0;");
        __syncthreads();
        if (it + 1 < 16) issue(it + 1);

        const int buf = it & 1;
        const float* Ab = As + buf * AS_BUF + (wm * 64) * AS_STRIDE;
        const float* Bb = Bs + buf * BS_BUF + wn * 32;

        #pragma unroll
        for (int ks = 0; ks < 4; ks++) {
            const int k0 = ks * 8;
            uint32_t ahi[4][4], alo[4][4];
            #pragma unroll
            for (int mt = 0; mt < 4; mt++) {
                int r0 = mt * 16 + qr;
                split3(Ab[r0 * AS_STRIDE + k0 + qc],           ahi[mt][0], alo[mt][0]);
                split3(Ab[(r0 + 8) * AS_STRIDE + k0 + qc],     ahi[mt][1], alo[mt][1]);
                split3(Ab[r0 * AS_STRIDE + k0 + qc + 4],       ahi[mt][2], alo[mt][2]);
                split3(Ab[(r0 + 8) * AS_STRIDE + k0 + qc + 4], ahi[mt][3], alo[mt][3]);
            }
            #pragma unroll
            for (int nt = 0; nt < 4; nt++) {
                uint32_t bhi0, blo0, bhi1, blo1;
                split3(Bb[(k0 + qc) * BS_STRIDE + nt * 8 + qr],     bhi0, blo0);
                split3(Bb[(k0 + qc + 4) * BS_STRIDE + nt * 8 + qr], bhi1, blo1);
                #pragma unroll
                for (int mt = 0; mt < 4; mt++) {
                    mma8(acc[mt][nt], alo[mt], bhi0, bhi1);   // small terms first
                    mma8(acc[mt][nt], ahi[mt], blo0, blo1);
                    mma8(acc[mt][nt], ahi[mt], bhi0, bhi1);
                }
            }
        }
    }

    // Epilogue: bias (+ optional residual + relu)
    #pragma unroll
    for (int mt = 0; mt < 4; mt++) {
        #pragma unroll
        for (int nt = 0; nt < 4; nt++) {
            int row = m0 + wm * 64 + mt * 16 + qr;
            int col = n0 + wn * 32 + nt * 8 + 2 * qc;
            float2 bv = *(const float2*)&bias[col];
            float2 v01, v23;
            v01.x = acc[mt][nt][0] + bv.x;
            v01.y = acc[mt][nt][1] + bv.y;
            v23.x = acc[mt][nt][2] + bv.x;
            v23.y = acc[mt][nt][3] + bv.y;
            if (epi == 1) {
                float2 r0 = *(const float2*)&resid[(size_t)row * EE + col];
                float2 r1 = *(const float2*)&resid[(size_t)(row + 8) * EE + col];
                v01.x = r0.x + fmaxf(v01.x, 0.0f);
                v01.y = r0.y + fmaxf(v01.y, 0.0f);
                v23.x = r1.x + fmaxf(v23.x, 0.0f);
                v23.y = r1.y + fmaxf(v23.y, 0.0f);
            }
            *(float2*)&C[(size_t)row * EE + col]       = v01;
            *(float2*)&C[(size_t)(row + 8) * EE + col] = v23;
        }
    }
}

// ---------------------------------------------------------------------------
// 3) Causal flash attention, 64x64 Q tile per CTA, D=64. fp32, float4 LDS
//    with 16B-unit XOR swizzle (unit' = unit ^ ((row>>2)&15)) on 64x64 tiles
//    (row stride 64 floats). Per-thread fmaf order identical to the verified
//    scalar version; only smem addressing changed.
// ---------------------------------------------------------------------------
#define ATT_SMEM (3 * 64 * 64 * 4)   // 49152 bytes

// float offset within a row for element (row, d)
__device__ __forceinline__ int sw_off(int row, int d)
{
    return ((((d) >> 2) ^ ((row >> 2) & 15)) << 2) | (d & 3);
}
// float offset for an aligned float4 at (row, d4) where d4 % 4 == 0
__device__ __forceinline__ int sw_off4(int row, int d4)
{
    return (((d4 >> 2) ^ ((row >> 2) & 15)) << 2);
}

__global__ __launch_bounds__(256) void attn_kernel(
    const float* __restrict__ Q, const float* __restrict__ K,
    const float* __restrict__ V, float* __restrict__ Out)
{
    extern __shared__ float sm[];
    float* Qs = sm;            // 64x64, swizzled
    float* Ks = sm + 4096;     // 64x64, swizzled (also holds P)
    float* Vs = sm + 8192;     // 64x64, swizzled

    const int qb = blockIdx.x, h = blockIdx.y, b = blockIdx.z;
    const int tid = threadIdx.x;
    const int ty = tid >> 4, tx = tid & 15;
    const int q0 = qb * 64;
    const size_t base = ((size_t)b * SS) * EE + h * DD;

    // Load Q tile (vectorized, swizzled store; conflict-free)
    for (int e = tid; e < 1024; e += 256) {
        int r = e >> 4, c4 = (e & 15) << 2;
        float4 v = *(const float4*)&Q[base + (size_t)(q0 + r) * EE + c4];
        *(float4*)&Qs[r * 64 + sw_off4(r, c4)] = v;
    }

    float mrow[4], lrow[4], o[4][4];
    #pragma unroll
    for (int r = 0; r < 4; r++) {
        mrow[r] = -CUDART_INF_F;
        lrow[r] = 0.0f;
        #pragma unroll
        for (int c = 0; c < 4; c++) o[r][c] = 0.0f;
    }

    for (int t = 0; t <= qb; t++) {
        const int k0 = t * 64;
        __syncthreads();   // prev-iter smem reads done (also guards first-iter Q)
        for (int e = tid; e < 1024; e += 256) {
            int r = e >> 4, c4 = (e & 15) << 2;
            int off = r * 64 + sw_off4(r, c4);
            size_t g = base + (size_t)(k0 + r) * EE + c4;
            *(float4*)&Ks[off] = *(const float4*)&K[g];
            *(float4*)&Vs[off] = *(const float4*)&V[g];
        }
        __syncthreads();

        // S = Q K^T  (4x4 per thread), d in float4 chunks
        float accS[4][4];
        #pragma unroll
        for (int r = 0; r < 4; r++)
            #pragma unroll
            for (int c = 0; c < 4; c++) accS[r][c] = 0.0f;

        #pragma unroll 4
        for (int d4 = 0; d4 < 64; d4 += 4) {
            float4 aq[4], bk[4];
            const int ua = ((d4 >> 2) ^ ty) << 2;   // rows ty*4+r: (row>>2)&15 == ty
            const int ub = ((d4 >> 2) ^ tx) << 2;   // rows tx*4+c: (row>>2)&15 == tx
            #pragma unroll
            for (int r = 0; r < 4; r++) aq[r] = *(const float4*)&Qs[(ty * 4 + r) * 64 + ua];
            #pragma unroll
            for (int c = 0; c < 4; c++) bk[c] = *(const float4*)&Ks[(tx * 4 + c) * 64 + ub];
            #pragma unroll
            for (int dd = 0; dd < 4; dd++) {
                #pragma unroll
                for (int r = 0; r < 4; r++) {
                    float av = ((const float*)&aq[r])[dd];
                    #pragma unroll
                    for (int c = 0; c < 4; c++)
                        accS[r][c] = fmaf(av, ((const float*)&bk[c])[dd], accS[r][c]);
                }
            }
        }

        // scale + causal mask + online softmax
        float p[4][4];
        const bool diag = (t == qb);
        #pragma unroll
        for (int r = 0; r < 4; r++) {
            float mx = -CUDART_INF_F;
            #pragma unroll
            for (int c = 0; c < 4; c++) {
                float s = accS[r][c] * 0.125f;
                if (diag && (tx * 4 + c) > (ty * 4 + r)) s = -CUDART_INF_F;
                accS[r][c] = s;
                mx = fmaxf(mx, s);
            }
            #pragma unroll
            for (int off = 8; off > 0; off >>= 1)
                mx = fmaxf(mx, __shfl_xor_sync(0xffffffffu, mx, off, 16));
            float mnew = fmaxf(mrow[r], mx);
            float alpha = __expf(mrow[r] - mnew);
            mrow[r] = mnew;
            float ls = 0.0f;
            #pragma unroll
            for (int c = 0; c < 4; c++) {
                float pv = __expf(accS[r][c] - mnew);
                p[r][c] = pv;
                ls += pv;
            }
            #pragma unroll
            for (int off = 8; off > 0; off >>= 1)
                ls += __shfl_xor_sync(0xffffffffu, ls, off, 16);
            lrow[r] = lrow[r] * alpha + ls;
            #pragma unroll
            for (int c = 0; c < 4; c++) o[r][c] *= alpha;
        }

        __syncthreads();   // everyone done reading Ks as K
        #pragma unroll
        for (int r = 0; r < 4; r++) {
            int row = ty * 4 + r;        // unit index for cols tx*4.. is tx ^ ty
            float4 pv = make_float4(p[r][0], p[r][1], p[r][2], p[r][3]);
            *(float4*)&Ks[row * 64 + ((tx ^ ty) << 2)] = pv;
        }
        __syncthreads();

        // O += P V   (P in Ks, V in Vs)
        #pragma unroll 8
        for (int j = 0; j < 64; j++) {
            float4 vv = *(const float4*)&Vs[j * 64 + ((tx ^ ((j >> 2) & 15)) << 2)];
            float pr[4];
            #pragma unroll
            for (int r = 0; r < 4; r++)
                pr[r] = Ks[(ty * 4 + r) * 64 + ((((j >> 2) ^ ty) << 2) | (j & 3))];
            #pragma unroll
            for (int r = 0; r < 4; r++) {
                o[r][0] = fmaf(pr[r], vv.x, o[r][0]);
                o[r][1] = fmaf(pr[r], vv.y, o[r][1]);
                o[r][2] = fmaf(pr[r], vv.z, o[r][2]);
                o[r][3] = fmaf(pr[r], vv.w, o[r][3]);
            }
        }
    }

    // Write output
    #pragma unroll
    for (int r = 0; r < 4; r++) {
        float inv = 1.0f / lrow[r];
        float4 v;
        v.x = o[r][0] * inv; v.y = o[r][1] * inv;
        v.z = o[r][2] * inv; v.w = o[r][3] * inv;
        *(float4*)&Out[base + (size_t)(q0 + ty * 4 + r) * EE + tx * 4] = v;
    }
}

// ---------------------------------------------------------------------------
// 4) Final projection: out[m] = dot(X[m,:], Wout[:,0]) + b_out[0]
// ---------------------------------------------------------------------------
__global__ __launch_bounds__(256) void outproj_kernel(
    const float* __restrict__ X, const float* __restrict__ Wout,
    const float* __restrict__ bout, float* __restrict__ out)
{
    int row  = blockIdx.x * 8 + (threadIdx.x >> 5);
    int lane = threadIdx.x & 31;
    const float* xr = X + (size_t)row * EE;
    float s = 0.0f;
    #pragma unroll
    for (int k = lane; k < EE; k += 32)
        s = fmaf(xr[k], Wout[k], s);
    #pragma unroll
    for (int off = 16; off > 0; off >>= 1)
        s += __shfl_xor_sync(0xffffffffu, s, off);
    if (lane == 0) out[row] = s + bout[0];
}

// ---------------------------------------------------------------------------
// Launcher
// ---------------------------------------------------------------------------
extern "C" void kernel_launch(void* const* d_in, const int* in_sizes, int n_in,
                              void* d_out, int out_size)
{
    const int*   inp   = (const int*)  d_in[0];
    const float* table = (const float*)d_in[1];
    const float* Wq    = (const float*)d_in[2];
    const float* bq    = (const float*)d_in[3];
    const float* Wk    = (const float*)d_in[4];
    const float* bk    = (const float*)d_in[5];
    const float* Wv    = (const float*)d_in[6];
    const float* bv    = (const float*)d_in[7];
    const float* Wo    = (const float*)d_in[8];
    const float* bo    = (const float*)d_in[9];
    const float* Wout  = (const float*)d_in[10];
    const float* bout  = (const float*)d_in[11];
    float* out = (float*)d_out;

    float *pX, *pQ, *pK, *pV, *pA;
    cudaGetSymbolAddress((void**)&pX, g_X);
    cudaGetSymbolAddress((void**)&pQ, g_Q);
    cudaGetSymbolAddress((void**)&pK, g_K);
    cudaGetSymbolAddress((void**)&pV, g_V);
    cudaGetSymbolAddress((void**)&pA, g_A);

    cudaFuncSetAttribute(attn_kernel,
                         cudaFuncAttributeMaxDynamicSharedMemorySize, ATT_SMEM);
    cudaFuncSetAttribute(gemm512_tc_kernel,
                         cudaFuncAttributeMaxDynamicSharedMemorySize, SMEM_GEMM);

    embed_pe_kernel<<<(int)(ELEMS / 256), 256>>>(inp, table, pX);

    dim3 ggrid(EE / 128, MM / 128);      // (4, 256)
    dim3 agrid(SS / 64, HH, BB);         // (16, 8, 32)

    for (int l = 0; l < LL; l++) {
        const float* wq = Wq + (size_t)l * EE * EE;
        const float* wk = Wk + (size_t)l * EE * EE;
        const float* wv = Wv + (size_t)l * EE * EE;
        const float* wo = Wo + (size_t)l * EE * EE;
        gemm512_tc_kernel<<<ggrid, 256, SMEM_GEMM>>>(pX, wq, bq + l * EE, pX, pQ, 0);
        gemm512_tc_kernel<<<ggrid, 256, SMEM_GEMM>>>(pX, wk, bk + l * EE, pX, pK, 0);
        gemm512_tc_kernel<<<ggrid, 256, SMEM_GEMM>>>(pX, wv, bv + l * EE, pX, pV, 0);
        attn_kernel<<<agrid, 256, ATT_SMEM>>>(pQ, pK, pV, pA);
        gemm512_tc_kernel<<<ggrid, 256, SMEM_GEMM>>>(pA, wo, bo + l * EE, pX, pX, 1);
    }

    outproj_kernel<<<MM / 8, 256>>>(pX, Wout, bout, out);
}

// round 7
// speedup vs baseline: 2.4386x; 2.0059x over previous
#include <cuda_runtime.h>
#include <cuda_bf16.h>
#include <math_constants.h>
#include <cstdint>

// Problem constants
#define BB   32
#define SS   1024
#define EE   512
#define HH   8
#define DD   64
#define LL   2
#define MM   (BB*SS)            // 32768
#define ELEMS ((size_t)MM*EE)   // 16,777,216

// Scratch (device globals; no allocation allowed)
__device__ float g_X[MM*EE];
__device__ float g_Q[MM*EE];
__device__ float g_K[MM*EE];
__device__ float g_V[MM*EE];
__device__ float g_A[MM*EE];

// ---------------------------------------------------------------------------
// tf32x3 primitives (verified in gemm512_tc_kernel)
// ---------------------------------------------------------------------------
__device__ __forceinline__ void split3(float x, uint32_t& hi, uint32_t& lo)
{
    uint32_t xb = __float_as_uint(x);
    hi = xb & 0xFFFFE000u;                 // truncate to tf32
    lo = __float_as_uint(x - __uint_as_float(hi));   // exact residual
}

__device__ __forceinline__ void mma8(float* d, const uint32_t* a,
                                     uint32_t b0, uint32_t b1)
{
    asm volatile(
        "mma.sync.aligned.m16n8k8.row.col.f32.tf32.tf32.f32 "
        "{%0,%1,%2,%3}, {%4,%5,%6,%7}, {%8,%9}, {%0,%1,%2,%3};"
        : "+f"(d[0]), "+f"(d[1]), "+f"(d[2]), "+f"(d[3])
        : "r"(a[0]), "r"(a[1]), "r"(a[2]), "r"(a[3]), "r"(b0), "r"(b1));
}

// ---------------------------------------------------------------------------
// 1) Embedding gather + positional encoding
// ---------------------------------------------------------------------------
__global__ void embed_pe_kernel(const int* __restrict__ inp,
                                const float* __restrict__ table,
                                float* __restrict__ X)
{
    int idx = blockIdx.x * 256 + threadIdx.x;          // over MM*EE
    int c  = idx & (EE - 1);
    int ms = idx >> 9;                                  // row in [0, MM)
    int s  = ms & (SS - 1);
    int tok = inp[ms];
    int i = c >> 1;
    float div = __expf((float)(2 * i) * (-9.210340371976184f / (float)EE));
    float ang = (float)s * div;
    float pe = (c & 1) ? cosf(ang) : sinf(ang);
    X[idx] = table[(size_t)tok * EE + c] + pe;
}

// ---------------------------------------------------------------------------
// 2) Tensor-core SGEMM via tf32x3 (UNCHANGED from verified R5 kernel)
// ---------------------------------------------------------------------------
#define AS_STRIDE 36
#define BS_STRIDE 136
#define AS_BUF (128 * AS_STRIDE)
#define BS_BUF (32 * BS_STRIDE)
#define SMEM_GEMM ((2 * AS_BUF + 2 * BS_BUF) * 4)   // 71,680 bytes

__global__ __launch_bounds__(256) void gemm512_tc_kernel(
    const float* __restrict__ A, const float* __restrict__ W,
    const float* __restrict__ bias, const float* __restrict__ resid,
    float* __restrict__ C, int epi)
{
    extern __shared__ float sm[];
    float* As = sm;
    float* Bs = sm + 2 * AS_BUF;

    const int tid  = threadIdx.x;
    const int lane = tid & 31;
    const int warp = tid >> 5;
    const int wm = warp & 1;
    const int wn = warp >> 1;
    const int qr = lane >> 2;
    const int qc = lane & 3;
    const int m0 = blockIdx.y * 128;
    const int n0 = blockIdx.x * 128;

    float acc[4][4][4];
    #pragma unroll
    for (int i = 0; i < 4; i++)
        #pragma unroll
        for (int j = 0; j < 4; j++)
            #pragma unroll
            for (int r = 0; r < 4; r++) acc[i][j][r] = 0.0f;

    auto issue = [&](int it) {
        int buf = it & 1;
        int k0 = it * 32;
        float* Asb = As + buf * AS_BUF;
        float* Bsb = Bs + buf * BS_BUF;
        #pragma unroll
        for (int p = 0; p < 4; p++) {
            int id = p * 256 + tid;
            int am = id >> 3, akc = id & 7;
            uint32_t sa = (uint32_t)__cvta_generic_to_shared(Asb + am * AS_STRIDE + akc * 4);
            const float* ga = A + (size_t)(m0 + am) * EE + k0 + akc * 4;
            asm volatile("cp.async.cg.shared.global [%0], [%1], 16;" :: "r"(sa), "l"(ga));
            int bk = id >> 5, bnc = id & 31;
            uint32_t sb = (uint32_t)__cvta_generic_to_shared(Bsb + bk * BS_STRIDE + bnc * 4);
            const float* gb = W + (size_t)(k0 + bk) * EE + n0 + bnc * 4;
            asm volatile("cp.async.cg.shared.global [%0], [%1], 16;" :: "r"(sb), "l"(gb));
        }
        asm volatile("cp.async.commit_group;");
    };

    issue(0);

    for (int it = 0; it < 16; it++) {
        asm volatile("cp.async.wait_group 0;");
        __syncthreads();
        if (it + 1 < 16) issue(it + 1);

        const int buf = it & 1;
        const float* Ab = As + buf * AS_BUF + (wm * 64) * AS_STRIDE;
        const float* Bb = Bs + buf * BS_BUF + wn * 32;

        #pragma unroll
        for (int ks = 0; ks < 4; ks++) {
            const int k0 = ks * 8;
            uint32_t ahi[4][4], alo[4][4];
            #pragma unroll
            for (int mt = 0; mt < 4; mt++) {
                int r0 = mt * 16 + qr;
                split3(Ab[r0 * AS_STRIDE + k0 + qc],           ahi[mt][0], alo[mt][0]);
                split3(Ab[(r0 + 8) * AS_STRIDE + k0 + qc],     ahi[mt][1], alo[mt][1]);
                split3(Ab[r0 * AS_STRIDE + k0 + qc + 4],       ahi[mt][2], alo[mt][2]);
                split3(Ab[(r0 + 8) * AS_STRIDE + k0 + qc + 4], ahi[mt][3], alo[mt][3]);
            }
            #pragma unroll
            for (int nt = 0; nt < 4; nt++) {
                uint32_t bhi0, blo0, bhi1, blo1;
                split3(Bb[(k0 + qc) * BS_STRIDE + nt * 8 + qr],     bhi0, blo0);
                split3(Bb[(k0 + qc + 4) * BS_STRIDE + nt * 8 + qr], bhi1, blo1);
                #pragma unroll
                for (int mt = 0; mt < 4; mt++) {
                    mma8(acc[mt][nt], alo[mt], bhi0, bhi1);
                    mma8(acc[mt][nt], ahi[mt], blo0, blo1);
                    mma8(acc[mt][nt], ahi[mt], bhi0, bhi1);
                }
            }
        }
    }

    #pragma unroll
    for (int mt = 0; mt < 4; mt++) {
        #pragma unroll
        for (int nt = 0; nt < 4; nt++) {
            int row = m0 + wm * 64 + mt * 16 + qr;
            int col = n0 + wn * 32 + nt * 8 + 2 * qc;
            float2 bv = *(const float2*)&bias[col];
            float2 v01, v23;
            v01.x = acc[mt][nt][0] + bv.x;
            v01.y = acc[mt][nt][1] + bv.y;
            v23.x = acc[mt][nt][2] + bv.x;
            v23.y = acc[mt][nt][3] + bv.y;
            if (epi == 1) {
                float2 r0 = *(const float2*)&resid[(size_t)row * EE + col];
                float2 r1 = *(const float2*)&resid[(size_t)(row + 8) * EE + col];
                v01.x = r0.x + fmaxf(v01.x, 0.0f);
                v01.y = r0.y + fmaxf(v01.y, 0.0f);
                v23.x = r1.x + fmaxf(v23.x, 0.0f);
                v23.y = r1.y + fmaxf(v23.y, 0.0f);
            }
            *(float2*)&C[(size_t)row * EE + col]       = v01;
            *(float2*)&C[(size_t)(row + 8) * EE + col] = v23;
        }
    }
}

// ---------------------------------------------------------------------------
// 3) Tensor-core causal flash attention (tf32x3, fp32-faithful).
//    128 q-rows per CTA, 8 warps x 16 rows. K/V tiles of 64 keys in smem
//    (stride 68). Online softmax on m16n8 C-fragment layout. P goes through
//    per-warp-private smem (syncwarp only). All mma inputs hi/lo split.
// ---------------------------------------------------------------------------
#define TST 68                                  // smem row stride (floats)
#define ATT_SMEM ((128*TST + 128*TST + 64*TST + 64*TST) * 4)   // 104,448 B

__global__ __launch_bounds__(256, 2) void attn_tc_kernel(
    const float* __restrict__ Q, const float* __restrict__ K,
    const float* __restrict__ V, float* __restrict__ Out)
{
    extern __shared__ float sm[];
    float* sQ = sm;                    // [128][TST]
    float* sP = sm + 128 * TST;        // [128][TST]
    float* sK = sm + 256 * TST;        // [64][TST]
    float* sV = sm + 320 * TST;        // [64][TST]

    const int qb = blockIdx.x, h = blockIdx.y, b = blockIdx.z;
    const int tid  = threadIdx.x;
    const int lane = tid & 31;
    const int w    = tid >> 5;          // warp 0..7
    const int qr   = lane >> 2;         // 0..7
    const int qc   = lane & 3;          // 0..3
    const int q0   = qb * 128;
    const int wr0  = w * 16;            // warp's local row base (0..112)
    const size_t base = ((size_t)b * SS) * EE + h * DD;

    // Load Q tile: 128 rows x 64 cols
    for (int e = tid; e < 128 * 16; e += 256) {
        int r = e >> 4, c4 = (e & 15) << 2;
        *(float4*)&sQ[r * TST + c4] =
            *(const float4*)&Q[base + (size_t)(q0 + r) * EE + c4];
    }

    float o[8][4];
    #pragma unroll
    for (int nt = 0; nt < 8; nt++)
        #pragma unroll
        for (int r = 0; r < 4; r++) o[nt][r] = 0.0f;
    float mA = -CUDART_INF_F, mB = -CUDART_INF_F;
    float lA = 0.0f, lB = 0.0f;

    const int nTiles = 2 * qb + 2;     // 64-key tiles covering causal range
    for (int t = 0; t < nTiles; t++) {
        const int k0 = t * 64;
        __syncthreads();               // prev-iter K/V reads complete
        for (int e = tid; e < 64 * 16; e += 256) {
            int r = e >> 4, c4 = (e & 15) << 2;
            size_t g = base + (size_t)(k0 + r) * EE + c4;
            int off = r * TST + c4;
            *(float4*)&sK[off] = *(const float4*)&K[g];
            *(float4*)&sV[off] = *(const float4*)&V[g];
        }
        __syncthreads();

        // fully-masked warp? (all keys beyond all of this warp's rows)
        if (k0 > q0 + wr0 + 15) continue;

        // ---- S = Q K^T : 16x64 per warp ----
        float accS[8][4];
        #pragma unroll
        for (int nt = 0; nt < 8; nt++)
            #pragma unroll
            for (int r = 0; r < 4; r++) accS[nt][r] = 0.0f;

        #pragma unroll
        for (int kc = 0; kc < 8; kc++) {
            const int kk = kc * 8;
            uint32_t qh[4], ql[4];
            split3(sQ[(wr0 + qr) * TST + kk + qc],         qh[0], ql[0]);
            split3(sQ[(wr0 + qr + 8) * TST + kk + qc],     qh[1], ql[1]);
            split3(sQ[(wr0 + qr) * TST + kk + qc + 4],     qh[2], ql[2]);
            split3(sQ[(wr0 + qr + 8) * TST + kk + qc + 4], qh[3], ql[3]);
            #pragma unroll
            for (int nt = 0; nt < 8; nt++) {
                uint32_t bh0, bl0, bh1, bl1;
                split3(sK[(nt * 8 + qr) * TST + kk + qc],     bh0, bl0);
                split3(sK[(nt * 8 + qr) * TST + kk + qc + 4], bh1, bl1);
                mma8(accS[nt], ql, bh0, bh1);
                mma8(accS[nt], qh, bl0, bl1);
                mma8(accS[nt], qh, bh0, bh1);
            }
        }

        // ---- scale + causal mask + online softmax ----
        const int rowA = q0 + wr0 + qr;     // global rows of this thread
        const int rowB = rowA + 8;
        const bool anymask = (k0 + 63 > q0 + wr0);
        float mxA = -CUDART_INF_F, mxB = -CUDART_INF_F;
        #pragma unroll
        for (int nt = 0; nt < 8; nt++) {
            float s0 = accS[nt][0] * 0.125f;
            float s1 = accS[nt][1] * 0.125f;
            float s2 = accS[nt][2] * 0.125f;
            float s3 = accS[nt][3] * 0.125f;
            if (anymask) {
                int key0 = k0 + nt * 8 + 2 * qc;
                int key1 = key0 + 1;
                if (key0 > rowA) s0 = -CUDART_INF_F;
                if (key1 > rowA) s1 = -CUDART_INF_F;
                if (key0 > rowB) s2 = -CUDART_INF_F;
                if (key1 > rowB) s3 = -CUDART_INF_F;
            }
            accS[nt][0] = s0; accS[nt][1] = s1;
            accS[nt][2] = s2; accS[nt][3] = s3;
            mxA = fmaxf(mxA, fmaxf(s0, s1));
            mxB = fmaxf(mxB, fmaxf(s2, s3));
        }
        mxA = fmaxf(mxA, __shfl_xor_sync(0xffffffffu, mxA, 1));
        mxA = fmaxf(mxA, __shfl_xor_sync(0xffffffffu, mxA, 2));
        mxB = fmaxf(mxB, __shfl_xor_sync(0xffffffffu, mxB, 1));
        mxB = fmaxf(mxB, __shfl_xor_sync(0xffffffffu, mxB, 2));

        float mnA = fmaxf(mA, mxA), mnB = fmaxf(mB, mxB);
        float aA = __expf(mA - mnA), aB = __expf(mB - mnB);
        mA = mnA; mB = mnB;

        float lsA = 0.0f, lsB = 0.0f;
        #pragma unroll
        for (int nt = 0; nt < 8; nt++) {
            float p0 = __expf(accS[nt][0] - mA);
            float p1 = __expf(accS[nt][1] - mA);
            float p2 = __expf(accS[nt][2] - mB);
            float p3 = __expf(accS[nt][3] - mB);
            lsA += p0 + p1;
            lsB += p2 + p3;
            int colp = nt * 8 + 2 * qc;
            *(float2*)&sP[(wr0 + qr) * TST + colp]     = make_float2(p0, p1);
            *(float2*)&sP[(wr0 + qr + 8) * TST + colp] = make_float2(p2, p3);
        }
        lsA += __shfl_xor_sync(0xffffffffu, lsA, 1);
        lsA += __shfl_xor_sync(0xffffffffu, lsA, 2);
        lsB += __shfl_xor_sync(0xffffffffu, lsB, 1);
        lsB += __shfl_xor_sync(0xffffffffu, lsB, 2);
        lA = lA * aA + lsA;
        lB = lB * aB + lsB;
        #pragma unroll
        for (int nt = 0; nt < 8; nt++) {
            o[nt][0] *= aA; o[nt][1] *= aA;
            o[nt][2] *= aB; o[nt][3] *= aB;
        }
        __syncwarp();      // P visible within warp

        // ---- O += P V : (16x64) @ (64x64) ----
        #pragma unroll
        for (int kc = 0; kc < 8; kc++) {
            const int kk = kc * 8;
            uint32_t ph[4], pl[4];
            split3(sP[(wr0 + qr) * TST + kk + qc],         ph[0], pl[0]);
            split3(sP[(wr0 + qr + 8) * TST + kk + qc],     ph[1], pl[1]);
            split3(sP[(wr0 + qr) * TST + kk + qc + 4],     ph[2], pl[2]);
            split3(sP[(wr0 + qr + 8) * TST + kk + qc + 4], ph[3], pl[3]);
            #pragma unroll
            for (int nt = 0; nt < 8; nt++) {
                uint32_t bh0, bl0, bh1, bl1;
                split3(sV[(kk + qc) * TST + nt * 8 + qr],     bh0, bl0);
                split3(sV[(kk + qc + 4) * TST + nt * 8 + qr], bh1, bl1);
                mma8(o[nt], pl, bh0, bh1);
                mma8(o[nt], ph, bl0, bl1);
                mma8(o[nt], ph, bh0, bh1);
            }
        }
    }

    // ---- write output ----
    const float invA = 1.0f / lA, invB = 1.0f / lB;
    const int rA = q0 + wr0 + qr, rB = rA + 8;
    #pragma unroll
    for (int nt = 0; nt < 8; nt++) {
        int col = nt * 8 + 2 * qc;
        *(float2*)&Out[base + (size_t)rA * EE + col] =
            make_float2(o[nt][0] * invA, o[nt][1] * invA);
        *(float2*)&Out[base + (size_t)rB * EE + col] =
            make_float2(o[nt][2] * invB, o[nt][3] * invB);
    }
}

// ---------------------------------------------------------------------------
// 4) Final projection: out[m] = dot(X[m,:], Wout[:,0]) + b_out[0]
// ---------------------------------------------------------------------------
__global__ __launch_bounds__(256) void outproj_kernel(
    const float* __restrict__ X, const float* __restrict__ Wout,
    const float* __restrict__ bout, float* __restrict__ out)
{
    int row  = blockIdx.x * 8 + (threadIdx.x >> 5);
    int lane = threadIdx.x & 31;
    const float* xr = X + (size_t)row * EE;
    float s = 0.0f;
    #pragma unroll
    for (int k = lane; k < EE; k += 32)
        s = fmaf(xr[k], Wout[k], s);
    #pragma unroll
    for (int off = 16; off > 0; off >>= 1)
        s += __shfl_xor_sync(0xffffffffu, s, off);
    if (lane == 0) out[row] = s + bout[0];
}

// ---------------------------------------------------------------------------
// Launcher
// ---------------------------------------------------------------------------
extern "C" void kernel_launch(void* const* d_in, const int* in_sizes, int n_in,
                              void* d_out, int out_size)
{
    const int*   inp   = (const int*)  d_in[0];
    const float* table = (const float*)d_in[1];
    const float* Wq    = (const float*)d_in[2];
    const float* bq    = (const float*)d_in[3];
    const float* Wk    = (const float*)d_in[4];
    const float* bk    = (const float*)d_in[5];
    const float* Wv    = (const float*)d_in[6];
    const float* bv    = (const float*)d_in[7];
    const float* Wo    = (const float*)d_in[8];
    const float* bo    = (const float*)d_in[9];
    const float* Wout  = (const float*)d_in[10];
    const float* bout  = (const float*)d_in[11];
    float* out = (float*)d_out;

    float *pX, *pQ, *pK, *pV, *pA;
    cudaGetSymbolAddress((void**)&pX, g_X);
    cudaGetSymbolAddress((void**)&pQ, g_Q);
    cudaGetSymbolAddress((void**)&pK, g_K);
    cudaGetSymbolAddress((void**)&pV, g_V);
    cudaGetSymbolAddress((void**)&pA, g_A);

    cudaFuncSetAttribute(attn_tc_kernel,
                         cudaFuncAttributeMaxDynamicSharedMemorySize, ATT_SMEM);
    cudaFuncSetAttribute(gemm512_tc_kernel,
                         cudaFuncAttributeMaxDynamicSharedMemorySize, SMEM_GEMM);

    embed_pe_kernel<<<(int)(ELEMS / 256), 256>>>(inp, table, pX);

    dim3 ggrid(EE / 128, MM / 128);      // (4, 256)
    dim3 agrid(SS / 128, HH, BB);        // (8, 8, 32)

    for (int l = 0; l < LL; l++) {
        const float* wq = Wq + (size_t)l * EE * EE;
        const float* wk = Wk + (size_t)l * EE * EE;
        const float* wv = Wv + (size_t)l * EE * EE;
        const float* wo = Wo + (size_t)l * EE * EE;
        gemm512_tc_kernel<<<ggrid, 256, SMEM_GEMM>>>(pX, wq, bq + l * EE, pX, pQ, 0);
        gemm512_tc_kernel<<<ggrid, 256, SMEM_GEMM>>>(pX, wk, bk + l * EE, pX, pK, 0);
        gemm512_tc_kernel<<<ggrid, 256, SMEM_GEMM>>>(pX, wv, bv + l * EE, pX, pV, 0);
        attn_tc_kernel<<<agrid, 256, ATT_SMEM>>>(pQ, pK, pV, pA);
        gemm512_tc_kernel<<<ggrid, 256, SMEM_GEMM>>>(pA, wo, bo + l * EE, pX, pX, 1);
    }

    outproj_kernel<<<MM / 8, 256>>>(pX, Wout, bout, out);
}

// round 10
// speedup vs baseline: 3.1332x; 1.2848x over previous
#include <cuda_runtime.h>
#include <cuda_bf16.h>
#include <math_constants.h>
#include <cstdint>

// Problem constants
#define BB   32
#define SS   1024
#define EE   512
#define HH   8
#define DD   64
#define LL   2
#define MM   (BB*SS)            // 32768
#define ELEMS ((size_t)MM*EE)   // 16,777,216

// Scratch (device globals; no allocation allowed)
__device__ float g_X[MM*EE];
__device__ float g_Q[MM*EE];
__device__ float g_K[MM*EE];
__device__ float g_V[MM*EE];
__device__ float g_A[MM*EE];

// ---------------------------------------------------------------------------
// tf32x3 primitives (used by attention; verified)
// ---------------------------------------------------------------------------
__device__ __forceinline__ void split3(float x, uint32_t& hi, uint32_t& lo)
{
    uint32_t xb = __float_as_uint(x);
    hi = xb & 0xFFFFE000u;                 // truncate to tf32
    lo = __float_as_uint(x - __uint_as_float(hi));   // exact residual
}

__device__ __forceinline__ void mma8(float* d, const uint32_t* a,
                                     uint32_t b0, uint32_t b1)
{
    asm volatile(
        "mma.sync.aligned.m16n8k8.row.col.f32.tf32.tf32.f32 "
        "{%0,%1,%2,%3}, {%4,%5,%6,%7}, {%8,%9}, {%0,%1,%2,%3};"
        : "+f"(d[0]), "+f"(d[1]), "+f"(d[2]), "+f"(d[3])
        : "r"(a[0]), "r"(a[1]), "r"(a[2]), "r"(a[3]), "r"(b0), "r"(b1));
}

// ---------------------------------------------------------------------------
// bf16x3 primitives (GEMM): x = hi(bf16) + lo(bf16), error ~2^-17 per product
// ---------------------------------------------------------------------------
__device__ __forceinline__ void bsplit2(float x0, float x1,
                                        uint32_t& hi, uint32_t& lo)
{
    uint32_t h;
    asm("cvt.rn.bf16x2.f32 %0, %1, %2;" : "=r"(h) : "f"(x1), "f"(x0));
    float h0 = __uint_as_float(h << 16);
    float h1 = __uint_as_float(h & 0xFFFF0000u);
    float l0 = x0 - h0;
    float l1 = x1 - h1;
    uint32_t l;
    asm("cvt.rn.bf16x2.f32 %0, %1, %2;" : "=r"(l) : "f"(l1), "f"(l0));
    hi = h; lo = l;
}

__device__ __forceinline__ void mma16(float* d, const uint32_t* a,
                                      uint32_t b0, uint32_t b1)
{
    asm volatile(
        "mma.sync.aligned.m16n8k16.row.col.f32.bf16.bf16.f32 "
        "{%0,%1,%2,%3}, {%4,%5,%6,%7}, {%8,%9}, {%0,%1,%2,%3};"
        : "+f"(d[0]), "+f"(d[1]), "+f"(d[2]), "+f"(d[3])
        : "r"(a[0]), "r"(a[1]), "r"(a[2]), "r"(a[3]), "r"(b0), "r"(b1));
}

// ---------------------------------------------------------------------------
// 1) Embedding gather + positional encoding
// ---------------------------------------------------------------------------
__global__ void embed_pe_kernel(const int* __restrict__ inp,
                                const float* __restrict__ table,
                                float* __restrict__ X)
{
    int idx = blockIdx.x * 256 + threadIdx.x;          // over MM*EE
    int c  = idx & (EE - 1);
    int ms = idx >> 9;                                  // row in [0, MM)
    int s  = ms & (SS - 1);
    int tok = inp[ms];
    int i = c >> 1;
    float div = __expf((float)(2 * i) * (-9.210340371976184f / (float)EE));
    float ang = (float)s * div;
    float pe = (c & 1) ? cosf(ang) : sinf(ang);
    X[idx] = table[(size_t)tok * EE + c] + pe;
}

// ---------------------------------------------------------------------------
// 2) Tensor-core SGEMM via bf16x3 (m16n8k16), 2 CTAs/SM.
//    C[M,512] = A[M,512] @ W[512,512] (+bias) (+residual/relu epilogue)
//    BM=BN=128, BK=32, 256 threads, warp grid 2(m)x4(n), warp tile 64x32.
//    As [m][40] (float2 frag loads phase-conflict-free),
//    Bs [k][132] (scalar frag loads conflict-free). cp.async double-buffered.
// ---------------------------------------------------------------------------
#define AS_STRIDE 40
#define BS_STRIDE 132
#define AS_BUF (128 * AS_STRIDE)   // 5120 floats per buffer
#define BS_BUF (32 * BS_STRIDE)    // 4224 floats per buffer
#define SMEM_GEMM ((2 * AS_BUF + 2 * BS_BUF) * 4)   // 74,752 bytes

__global__ __launch_bounds__(256, 2) void gemm512_tc_kernel(
    const float* __restrict__ A, const float* __restrict__ W,
    const float* __restrict__ bias, const float* __restrict__ resid,
    float* __restrict__ C, int epi)
{
    extern __shared__ float sm[];
    float* As = sm;
    float* Bs = sm + 2 * AS_BUF;

    const int tid  = threadIdx.x;
    const int lane = tid & 31;
    const int warp = tid >> 5;
    const int wm = warp & 1;
    const int wn = warp >> 1;
    const int qr = lane >> 2;
    const int qc = lane & 3;
    const int m0 = blockIdx.y * 128;
    const int n0 = blockIdx.x * 128;

    float acc[4][4][4];
    #pragma unroll
    for (int i = 0; i < 4; i++)
        #pragma unroll
        for (int j = 0; j < 4; j++)
            #pragma unroll
            for (int r = 0; r < 4; r++) acc[i][j][r] = 0.0f;

    auto issue = [&](int it) {
        int buf = it & 1;
        int k0 = it * 32;
        float* Asb = As + buf * AS_BUF;
        float* Bsb = Bs + buf * BS_BUF;
        #pragma unroll
        for (int p = 0; p < 4; p++) {
            int id = p * 256 + tid;
            int am = id >> 3, akc = id & 7;
            uint32_t sa = (uint32_t)__cvta_generic_to_shared(Asb + am * AS_STRIDE + akc * 4);
            const float* ga = A + (size_t)(m0 + am) * EE + k0 + akc * 4;
            asm volatile("cp.async.cg.shared.global [%0], [%1], 16;" :: "r"(sa), "l"(ga));
            int bk = id >> 5, bnc = (id & 31) * 4;
            uint32_t sb = (uint32_t)__cvta_generic_to_shared(Bsb + bk * BS_STRIDE + bnc);
            const float* gb = W + (size_t)(k0 + bk) * EE + n0 + bnc;
            asm volatile("cp.async.cg.shared.global [%0], [%1], 16;" :: "r"(sb), "l"(gb));
        }
        asm volatile("cp.async.commit_group;");
    };

    issue(0);

    for (int it = 0; it < 16; it++) {
        asm volatile("cp.async.wait_group 0;");
        __syncthreads();
        if (it + 1 < 16) issue(it + 1);

        const int buf = it & 1;
        const float* Ab = As + buf * AS_BUF + (wm * 64) * AS_STRIDE;
        const float* Bb = Bs + buf * BS_BUF + wn * 32;

        #pragma unroll
        for (int kc = 0; kc < 2; kc++) {
            const int kk = kc * 16;
            uint32_t ahi[4][4], alo[4][4];
            #pragma unroll
            for (int mt = 0; mt < 4; mt++) {
                int r0 = mt * 16 + qr;
                float2 p0 = *(const float2*)&Ab[r0 * AS_STRIDE + kk + 2 * qc];
                float2 p1 = *(const float2*)&Ab[(r0 + 8) * AS_STRIDE + kk + 2 * qc];
                float2 p2 = *(const float2*)&Ab[r0 * AS_STRIDE + kk + 2 * qc + 8];
                float2 p3 = *(const float2*)&Ab[(r0 + 8) * AS_STRIDE + kk + 2 * qc + 8];
                bsplit2(p0.x, p0.y, ahi[mt][0], alo[mt][0]);
                bsplit2(p1.x, p1.y, ahi[mt][1], alo[mt][1]);
                bsplit2(p2.x, p2.y, ahi[mt][2], alo[mt][2]);
                bsplit2(p3.x, p3.y, ahi[mt][3], alo[mt][3]);
            }
            #pragma unroll
            for (int nt = 0; nt < 4; nt++) {
                const int nn = nt * 8 + qr;
                float x0 = Bb[(kk + 2 * qc) * BS_STRIDE + nn];
                float x1 = Bb[(kk + 2 * qc + 1) * BS_STRIDE + nn];
                float x2 = Bb[(kk + 2 * qc + 8) * BS_STRIDE + nn];
                float x3 = Bb[(kk + 2 * qc + 9) * BS_STRIDE + nn];
                uint32_t bh0, bl0, bh1, bl1;
                bsplit2(x0, x1, bh0, bl0);
                bsplit2(x2, x3, bh1, bl1);
                #pragma unroll
                for (int mt = 0; mt < 4; mt++) {
                    mma16(acc[mt][nt], alo[mt], bh0, bh1);   // small terms first
                    mma16(acc[mt][nt], ahi[mt], bl0, bl1);
                    mma16(acc[mt][nt], ahi[mt], bh0, bh1);
                }
            }
        }
    }

    // Epilogue: bias (+ optional residual + relu)
    #pragma unroll
    for (int mt = 0; mt < 4; mt++) {
        #pragma unroll
        for (int nt = 0; nt < 4; nt++) {
            int row = m0 + wm * 64 + mt * 16 + qr;
            int col = n0 + wn * 32 + nt * 8 + 2 * qc;
            float2 bv = *(const float2*)&bias[col];
            float2 v01, v23;
            v01.x = acc[mt][nt][0] + bv.x;
            v01.y = acc[mt][nt][1] + bv.y;
            v23.x = acc[mt][nt][2] + bv.x;
            v23.y = acc[mt][nt][3] + bv.y;
            if (epi == 1) {
                float2 r0 = *(const float2*)&resid[(size_t)row * EE + col];
                float2 r1 = *(const float2*)&resid[(size_t)(row + 8) * EE + col];
                v01.x = r0.x + fmaxf(v01.x, 0.0f);
                v01.y = r0.y + fmaxf(v01.y, 0.0f);
                v23.x = r1.x + fmaxf(v23.x, 0.0f);
                v23.y = r1.y + fmaxf(v23.y, 0.0f);
            }
            *(float2*)&C[(size_t)row * EE + col]       = v01;
            *(float2*)&C[(size_t)(row + 8) * EE + col] = v23;
        }
    }
}

// ---------------------------------------------------------------------------
// 3) Tensor-core causal flash attention (tf32x3) — UNCHANGED from verified R7
// ---------------------------------------------------------------------------
#define TST 68                                  // smem row stride (floats)
#define ATT_SMEM ((128*TST + 128*TST + 64*TST + 64*TST) * 4)   // 104,448 B

__global__ __launch_bounds__(256, 2) void attn_tc_kernel(
    const float* __restrict__ Q, const float* __restrict__ K,
    const float* __restrict__ V, float* __restrict__ Out)
{
    extern __shared__ float sm[];
    float* sQ = sm;                    // [128][TST]
    float* sP = sm + 128 * TST;        // [128][TST]
    float* sK = sm + 256 * TST;        // [64][TST]
    float* sV = sm + 320 * TST;        // [64][TST]

    const int qb = blockIdx.x, h = blockIdx.y, b = blockIdx.z;
    const int tid  = threadIdx.x;
    const int lane = tid & 31;
    const int w    = tid >> 5;          // warp 0..7
    const int qr   = lane >> 2;         // 0..7
    const int qc   = lane & 3;          // 0..3
    const int q0   = qb * 128;
    const int wr0  = w * 16;            // warp's local row base (0..112)
    const size_t base = ((size_t)b * SS) * EE + h * DD;

    for (int e = tid; e < 128 * 16; e += 256) {
        int r = e >> 4, c4 = (e & 15) << 2;
        *(float4*)&sQ[r * TST + c4] =
            *(const float4*)&Q[base + (size_t)(q0 + r) * EE + c4];
    }

    float o[8][4];
    #pragma unroll
    for (int nt = 0; nt < 8; nt++)
        #pragma unroll
        for (int r = 0; r < 4; r++) o[nt][r] = 0.0f;
    float mA = -CUDART_INF_F, mB = -CUDART_INF_F;
    float lA = 0.0f, lB = 0.0f;

    const int nTiles = 2 * qb + 2;
    for (int t = 0; t < nTiles; t++) {
        const int k0 = t * 64;
        __syncthreads();
        for (int e = tid; e < 64 * 16; e += 256) {
            int r = e >> 4, c4 = (e & 15) << 2;
            size_t g = base + (size_t)(k0 + r) * EE + c4;
            int off = r * TST + c4;
            *(float4*)&sK[off] = *(const float4*)&K[g];
            *(float4*)&sV[off] = *(const float4*)&V[g];
        }
        __syncthreads();

        if (k0 > q0 + wr0 + 15) continue;

        float accS[8][4];
        #pragma unroll
        for (int nt = 0; nt < 8; nt++)
            #pragma unroll
            for (int r = 0; r < 4; r++) accS[nt][r] = 0.0f;

        #pragma unroll
        for (int kc = 0; kc < 8; kc++) {
            const int kk = kc * 8;
            uint32_t qh[4], ql[4];
            split3(sQ[(wr0 + qr) * TST + kk + qc],         qh[0], ql[0]);
            split3(sQ[(wr0 + qr + 8) * TST + kk + qc],     qh[1], ql[1]);
            split3(sQ[(wr0 + qr) * TST + kk + qc + 4],     qh[2], ql[2]);
            split3(sQ[(wr0 + qr + 8) * TST + kk + qc + 4], qh[3], ql[3]);
            #pragma unroll
            for (int nt = 0; nt < 8; nt++) {
                uint32_t bh0, bl0, bh1, bl1;
                split3(sK[(nt * 8 + qr) * TST + kk + qc],     bh0, bl0);
                split3(sK[(nt * 8 + qr) * TST + kk + qc + 4], bh1, bl1);
                mma8(accS[nt], ql, bh0, bh1);
                mma8(accS[nt], qh, bl0, bl1);
                mma8(accS[nt], qh, bh0, bh1);
            }
        }

        const int rowA = q0 + wr0 + qr;
        const int rowB = rowA + 8;
        const bool anymask = (k0 + 63 > q0 + wr0);
        float mxA = -CUDART_INF_F, mxB = -CUDART_INF_F;
        #pragma unroll
        for (int nt = 0; nt < 8; nt++) {
            float s0 = accS[nt][0] * 0.125f;
            float s1 = accS[nt][1] * 0.125f;
            float s2 = accS[nt][2] * 0.125f;
            float s3 = accS[nt][3] * 0.125f;
            if (anymask) {
                int key0 = k0 + nt * 8 + 2 * qc;
                int key1 = key0 + 1;
                if (key0 > rowA) s0 = -CUDART_INF_F;
                if (key1 > rowA) s1 = -CUDART_INF_F;
                if (key0 > rowB) s2 = -CUDART_INF_F;
                if (key1 > rowB) s3 = -CUDART_INF_F;
            }
            accS[nt][0] = s0; accS[nt][1] = s1;
            accS[nt][2] = s2; accS[nt][3] = s3;
            mxA = fmaxf(mxA, fmaxf(s0, s1));
            mxB = fmaxf(mxB, fmaxf(s2, s3));
        }
        mxA = fmaxf(mxA, __shfl_xor_sync(0xffffffffu, mxA, 1));
        mxA = fmaxf(mxA, __shfl_xor_sync(0xffffffffu, mxA, 2));
        mxB = fmaxf(mxB, __shfl_xor_sync(0xffffffffu, mxB, 1));
        mxB = fmaxf(mxB, __shfl_xor_sync(0xffffffffu, mxB, 2));

        float mnA = fmaxf(mA, mxA), mnB = fmaxf(mB, mxB);
        float aA = __expf(mA - mnA), aB = __expf(mB - mnB);
        mA = mnA; mB = mnB;

        float lsA = 0.0f, lsB = 0.0f;
        #pragma unroll
        for (int nt = 0; nt < 8; nt++) {
            float p0 = __expf(accS[nt][0] - mA);
            float p1 = __expf(accS[nt][1] - mA);
            float p2 = __expf(accS[nt][2] - mB);
            float p3 = __expf(accS[nt][3] - mB);
            lsA += p0 + p1;
            lsB += p2 + p3;
            int colp = nt * 8 + 2 * qc;
            *(float2*)&sP[(wr0 + qr) * TST + colp]     = make_float2(p0, p1);
            *(float2*)&sP[(wr0 + qr + 8) * TST + colp] = make_float2(p2, p3);
        }
        lsA += __shfl_xor_sync(0xffffffffu, lsA, 1);
        lsA += __shfl_xor_sync(0xffffffffu, lsA, 2);
        lsB += __shfl_xor_sync(0xffffffffu, lsB, 1);
        lsB += __shfl_xor_sync(0xffffffffu, lsB, 2);
        lA = lA * aA + lsA;
        lB = lB * aB + lsB;
        #pragma unroll
        for (int nt = 0; nt < 8; nt++) {
            o[nt][0] *= aA; o[nt][1] *= aA;
            o[nt][2] *= aB; o[nt][3] *= aB;
        }
        __syncwarp();

        #pragma unroll
        for (int kc = 0; kc < 8; kc++) {
            const int kk = kc * 8;
            uint32_t ph[4], pl[4];
            split3(sP[(wr0 + qr) * TST + kk + qc],         ph[0], pl[0]);
            split3(sP[(wr0 + qr + 8) * TST + kk + qc],     ph[1], pl[1]);
            split3(sP[(wr0 + qr) * TST + kk + qc + 4],     ph[2], pl[2]);
            split3(sP[(wr0 + qr + 8) * TST + kk + qc + 4], ph[3], pl[3]);
            #pragma unroll
            for (int nt = 0; nt < 8; nt++) {
                uint32_t bh0, bl0, bh1, bl1;
                split3(sV[(kk + qc) * TST + nt * 8 + qr],     bh0, bl0);
                split3(sV[(kk + qc + 4) * TST + nt * 8 + qr], bh1, bl1);
                mma8(o[nt], pl, bh0, bh1);
                mma8(o[nt], ph, bl0, bl1);
                mma8(o[nt], ph, bh0, bh1);
            }
        }
    }

    const float invA = 1.0f / lA, invB = 1.0f / lB;
    const int rA = q0 + wr0 + qr, rB = rA + 8;
    #pragma unroll
    for (int nt = 0; nt < 8; nt++) {
        int col = nt * 8 + 2 * qc;
        *(float2*)&Out[base + (size_t)rA * EE + col] =
            make_float2(o[nt][0] * invA, o[nt][1] * invA);
        *(float2*)&Out[base + (size_t)rB * EE + col] =
            make_float2(o[nt][2] * invB, o[nt][3] * invB);
    }
}

// ---------------------------------------------------------------------------
// 4) Final projection: out[m] = dot(X[m,:], Wout[:,0]) + b_out[0]
// ---------------------------------------------------------------------------
__global__ __launch_bounds__(256) void outproj_kernel(
    const float* __restrict__ X, const float* __restrict__ Wout,
    const float* __restrict__ bout, float* __restrict__ out)
{
    int row  = blockIdx.x * 8 + (threadIdx.x >> 5);
    int lane = threadIdx.x & 31;
    const float* xr = X + (size_t)row * EE;
    float s = 0.0f;
    #pragma unroll
    for (int k = lane; k < EE; k += 32)
        s = fmaf(xr[k], Wout[k], s);
    #pragma unroll
    for (int off = 16; off > 0; off >>= 1)
        s += __shfl_xor_sync(0xffffffffu, s, off);
    if (lane == 0) out[row] = s + bout[0];
}

// ---------------------------------------------------------------------------
// Launcher
// ---------------------------------------------------------------------------
extern "C" void kernel_launch(void* const* d_in, const int* in_sizes, int n_in,
                              void* d_out, int out_size)
{
    const int*   inp   = (const int*)  d_in[0];
    const float* table = (const float*)d_in[1];
    const float* Wq    = (const float*)d_in[2];
    const float* bq    = (const float*)d_in[3];
    const float* Wk    = (const float*)d_in[4];
    const float* bk    = (const float*)d_in[5];
    const float* Wv    = (const float*)d_in[6];
    const float* bv    = (const float*)d_in[7];
    const float* Wo    = (const float*)d_in[8];
    const float* bo    = (const float*)d_in[9];
    const float* Wout  = (const float*)d_in[10];
    const float* bout  = (const float*)d_in[11];
    float* out = (float*)d_out;

    float *pX, *pQ, *pK, *pV, *pA;
    cudaGetSymbolAddress((void**)&pX, g_X);
    cudaGetSymbolAddress((void**)&pQ, g_Q);
    cudaGetSymbolAddress((void**)&pK, g_K);
    cudaGetSymbolAddress((void**)&pV, g_V);
    cudaGetSymbolAddress((void**)&pA, g_A);

    cudaFuncSetAttribute(attn_tc_kernel,
                         cudaFuncAttributeMaxDynamicSharedMemorySize, ATT_SMEM);
    cudaFuncSetAttribute(gemm512_tc_kernel,
                         cudaFuncAttributeMaxDynamicSharedMemorySize, SMEM_GEMM);

    embed_pe_kernel<<<(int)(ELEMS / 256), 256>>>(inp, table, pX);

    dim3 ggrid(EE / 128, MM / 128);      // (4, 256)
    dim3 agrid(SS / 128, HH, BB);        // (8, 8, 32)

    for (int l = 0; l < LL; l++) {
        const float* wq = Wq + (size_t)l * EE * EE;
        const float* wk = Wk + (size_t)l * EE * EE;
        const float* wv = Wv + (size_t)l * EE * EE;
        const float* wo = Wo + (size_t)l * EE * EE;
        gemm512_tc_kernel<<<ggrid, 256, SMEM_GEMM>>>(pX, wq, bq + l * EE, pX, pQ, 0);
        gemm512_tc_kernel<<<ggrid, 256, SMEM_GEMM>>>(pX, wk, bk + l * EE, pX, pK, 0);
        gemm512_tc_kernel<<<ggrid, 256, SMEM_GEMM>>>(pX, wv, bv + l * EE, pX, pV, 0);
        attn_tc_kernel<<<agrid, 256, ATT_SMEM>>>(pQ, pK, pV, pA);
        gemm512_tc_kernel<<<ggrid, 256, SMEM_GEMM>>>(pA, wo, bo + l * EE, pX, pX, 1);
    }

    outproj_kernel<<<MM / 8, 256>>>(pX, Wout, bout, out);
}